// round 11
// baseline (speedup 1.0000x reference)
#include <cuda_runtime.h>
#include <stdint.h>

#define NQ      8
#define NPAIRS  28
#define NB      16384
#define THREADS 128

typedef unsigned long long u64;

// ---------------- f32x2 packed helpers ----------------
__device__ __forceinline__ u64 pk(float lo, float hi) {
    u64 v; asm("mov.b64 %0, {%1, %2};" : "=l"(v) : "f"(lo), "f"(hi)); return v;
}
__device__ __forceinline__ void upk(u64 v, float& lo, float& hi) {
    asm("mov.b64 {%0, %1}, %2;" : "=f"(lo), "=f"(hi) : "l"(v));
}
__device__ __forceinline__ u64 bc2(float x) { return pk(x, x); }
__device__ __forceinline__ u64 sw2(u64 v) {
    float lo, hi; upk(v, lo, hi); return pk(hi, lo);
}
__device__ __forceinline__ u64 fma2(u64 a, u64 b, u64 c) {
    u64 d; asm("fma.rn.f32x2 %0, %1, %2, %3;" : "=l"(d) : "l"(a), "l"(b), "l"(c)); return d;
}
__device__ __forceinline__ u64 mul2(u64 a, u64 b) {
    u64 d; asm("mul.rn.f32x2 %0, %1, %2;" : "=l"(d) : "l"(a), "l"(b)); return d;
}

// ---------------- gate primitives ----------------
// Lane-qubit RY via per-warp SMEM slab exchange (no shuffles, no pack MOVs).
__device__ __forceinline__ void ry_lane_sm(u64 (&a)[8], float c, float s,
                                           int mask, unsigned lam,
                                           u64 (*slab)[32], unsigned lane) {
    __syncwarp();
#pragma unroll
    for (int r = 0; r < 8; r++) slab[r][lane] = a[r];
    __syncwarp();
    const u64 c2 = bc2(c);
    const u64 sg2 = bc2(lam ? s : -s);
#pragma unroll
    for (int r = 0; r < 8; r++) {
        u64 p = slab[r][lane ^ mask];
        a[r] = fma2(sg2, p, mul2(c2, a[r]));
    }
}

__device__ __forceinline__ void ry_reg_m(u64 (&a)[8], float c, float s, int m) {
    const u64 c2 = bc2(c), s2 = bc2(s), ns2 = bc2(-s);
#pragma unroll
    for (int r = 0; r < 8; r++) {
        if (!(r & m)) {
            u64 x = a[r], y = a[r | m];
            a[r]     = fma2(ns2, y, mul2(c2, x));
            a[r | m] = fma2(s2,  x, mul2(c2, y));
        }
    }
}

__device__ __forceinline__ float lane_wht(float v, unsigned lane) {
#pragma unroll
    for (int m = 1; m < 32; m <<= 1) {
        float t = __shfl_xor_sync(0xffffffffu, v, m);
        v = (lane & m) ? (t - v) : (v + t);
    }
    return v;
}

// ---------------- single fused kernel ----------------

__global__ void __launch_bounds__(THREADS, 8)
vqc_kernel(const float4* __restrict__ theta4, const float4* __restrict__ phi4,
           const float4* __restrict__ jup4, const float* __restrict__ w,
           float* __restrict__ out) {
    // block-shared batch-independent tables + per-warp exchange slabs
    __shared__ float2 s_cs[2 * NQ];      // cos/sin(theta_w/2) per (layer,qubit)
    __shared__ float2 s_hw[NQ];          // (0.5*phi_w(l0), 0.5*phi_w(l1)-0.25*phi_w(l0))
    __shared__ u64    s_d2t[8][32];      // DIAG2 complex factor, transposed [r][lane]
    __shared__ u64    s_x[THREADS / 32][8][32];   // exchange slabs (8KB)

    const unsigned t    = threadIdx.x;
    const unsigned tid  = blockIdx.x * THREADS + t;
    const unsigned b    = tid >> 5;
    const unsigned lane = tid & 31;
    u64 (*slab)[32] = s_x[t >> 5];

    // ---- cooperative table build ----
    if (t < 2 * NQ) {
        float c, s;
        __sincosf(0.5f * w[t * 3 + 1], &s, &c);
        s_cs[t] = make_float2(c, s);
    } else if (t < 3 * NQ) {
        int i = t - 2 * NQ;
        float w0p = w[i * 3], w1p = w[(NQ + i) * 3];
        s_hw[i] = make_float2(0.5f * w0p, fmaf(-0.25f, w0p, 0.5f * w1p));
    }
    {
        int idx = (int)t * 2;            // even entry; odd differs only in r bit0
        int ln = idx >> 3, r0 = idx & 7;
        float h[8];
#pragma unroll
        for (int k = 0; k < 8; k++) h[k] = 0.5f * w[k * 3 + 2];
        float phr = 0.f;
#pragma unroll
        for (int k = 0; k < 5; k++)
            phr += ((ln >> (4 - k)) & 1) ? h[k] : -h[k];
        phr += ((r0 >> 2) & 1) ? h[5] : -h[5];
        phr += ((r0 >> 1) & 1) ? h[6] : -h[6];
        phr -= h[7];
        float ss, cc;
        __sincosf(phr, &ss, &cc);
        s_d2t[r0][ln] = pk(cc, ss);
        __sincosf(phr + 2.f * h[7], &ss, &cc);
        s_d2t[r0 + 1][ln] = pk(cc, ss);
    }
    __syncthreads();

    // ---- vectorized warp-uniform input loads ----
    float th[NQ], phv[NQ], J[NPAIRS];
    {
        float4 t0 = theta4[b * 2], t1 = theta4[b * 2 + 1];
        th[0]=t0.x; th[1]=t0.y; th[2]=t0.z; th[3]=t0.w;
        th[4]=t1.x; th[5]=t1.y; th[6]=t1.z; th[7]=t1.w;
        float4 p0 = phi4[b * 2], p1 = phi4[b * 2 + 1];
        phv[0]=p0.x; phv[1]=p0.y; phv[2]=p0.z; phv[3]=p0.w;
        phv[4]=p1.x; phv[5]=p1.y; phv[6]=p1.z; phv[7]=p1.w;
#pragma unroll
        for (int q = 0; q < 7; q++) {
            float4 jv = jup4[b * 7 + q];
            J[q*4+0]=jv.x; J[q*4+1]=jv.y; J[q*4+2]=jv.z; J[q*4+3]=jv.w;
        }
    }

    float hc1[NQ];          // 0.5*phi + 0.5*phi_w(l0)
    float cq[NQ], sq[NQ];   // cos/sin(theta/4)
    float ch[NQ], sh[NQ];   // cos/sin(theta/2) via double-angle
#pragma unroll
    for (int k = 0; k < NQ; k++) {
        hc1[k] = fmaf(0.5f, phv[k], s_hw[k].x);
        __sincosf(0.25f * th[k], &sq[k], &cq[k]);
        sh[k] = 2.f * sq[k] * cq[k];
        ch[k] = fmaf(-2.f * sq[k], sq[k], 1.f);
    }

    // ===== Ising Walsh table over reg bits (lane part in index 0) =====
    float exr[8];
    {
        const float HP = 1.5707963267948966f;
        float sg[5];
#pragma unroll
        for (int k = 0; k < 5; k++)
            sg[k] = ((lane >> (4 - k)) & 1) ? 1.f : -1.f;
        float il = 0.f;
        {
            const int PI[10] = {0,0,0,0, 1,1,1, 2,2, 3};
            const int PJ[10] = {1,2,3,4, 2,3,4, 3,4, 4};
            const int PP[10] = {0,1,2,3, 7,8,9, 13,14, 18};
#pragma unroll
            for (int q = 0; q < 10; q++)
                il = fmaf(-sg[PI[q]] * sg[PJ[q]], J[PP[q]], il);
        }
        float U0 = 0.f, U1 = 0.f, U2 = 0.f;
        {
            const int P5[5] = {4, 10, 15, 19, 22};
#pragma unroll
            for (int i = 0; i < 5; i++) {
                U0 = fmaf(sg[i], J[P5[i]],     U0);
                U1 = fmaf(sg[i], J[P5[i] + 1], U1);
                U2 = fmaf(sg[i], J[P5[i] + 2], U2);
            }
        }
        float J56 = J[25], J57 = J[26], J67 = J[27];
        exr[0] = il * HP;  exr[1] = U2 * HP;   exr[2] = U1 * HP;  exr[3] = -J67 * HP;
        exr[4] = U0 * HP;  exr[5] = -J57 * HP; exr[6] = -J56 * HP; exr[7] = 0.f;
    }

    // ===== Fused: product state after encoding RY + DIAG1 phase =====
    u64 a[8];
    {
        float base = 0.f;
#pragma unroll
        for (int k = 0; k < 5; k++)
            base += ((lane >> (4 - k)) & 1) ? hc1[k] : -hc1[k];
        float w0[8];
        w0[0] = base + exr[0];   w0[1] = exr[1] - hc1[7];
        w0[2] = exr[2] - hc1[6]; w0[3] = exr[3];
        w0[4] = exr[4] - hc1[5]; w0[5] = exr[5];
        w0[6] = exr[6];          w0[7] = exr[7];
#pragma unroll
        for (int st = 1; st < 8; st <<= 1) {
#pragma unroll
            for (int i = 0; i < 8; i++) {
                if (!(i & st)) {
                    float u = w0[i], v = w0[i | st];
                    w0[i] = u + v; w0[i | st] = u - v;
                }
            }
        }
        float lf = 1.f;
#pragma unroll
        for (int k = 0; k < 5; k++)
            lf *= ((lane >> (4 - k)) & 1) ? sh[k] : ch[k];
        float f56[4];
        f56[0] = ch[5] * ch[6]; f56[1] = ch[5] * sh[6];
        f56[2] = sh[5] * ch[6]; f56[3] = sh[5] * sh[6];
#pragma unroll
        for (int r = 0; r < 8; r++) {
            float v = lf * f56[r >> 1] * ((r & 1) ? sh[7] : ch[7]);
            float phr = w0[r];
            float q = rintf(phr * 0.15915494309189535f);
            phr = fmaf(q, -6.2831855f, phr);
            float cc, ss;
            __sincosf(phr, &ss, &cc);
            a[r] = pk(v * cc, v * ss);
        }
    }

    // ===== Round A: layer 0 Rot-RY (lane gates via SMEM exchange) =====
    {
        ry_lane_sm(a, s_cs[0].x, s_cs[0].y, 16, (lane >> 4) & 1u, slab, lane);
        ry_lane_sm(a, s_cs[1].x, s_cs[1].y,  8, (lane >> 3) & 1u, slab, lane);
        ry_lane_sm(a, s_cs[2].x, s_cs[2].y,  4, (lane >> 2) & 1u, slab, lane);
        ry_lane_sm(a, s_cs[3].x, s_cs[3].y,  2, (lane >> 1) & 1u, slab, lane);
        ry_lane_sm(a, s_cs[4].x, s_cs[4].y,  1,  lane       & 1u, slab, lane);
        ry_reg_m(a, s_cs[5].x, s_cs[5].y, 4);
        ry_reg_m(a, s_cs[6].x, s_cs[6].y, 2);
        ry_reg_m(a, s_cs[7].x, s_cs[7].y, 1);
    }

    // ===== DIAG2 via block-shared complex table =====
#pragma unroll
    for (int r = 0; r < 8; r++) {
        u64 v = s_d2t[r][lane];
        float cc, ss, x, y;
        upk(v, cc, ss); upk(a[r], x, y);
        a[r] = pk(fmaf(cc, x, -ss * y), fmaf(cc, y, ss * x));
    }

    // ===== CNOT ring 1: lane part folded into relabeling =====
    const unsigned lam4 = (lane >> 4) & 1u;
    const unsigned lam3 = lam4 ^ ((lane >> 3) & 1u);
    const unsigned lam2 = lam3 ^ ((lane >> 2) & 1u);
    const unsigned lam1 = lam2 ^ ((lane >> 1) & 1u);
    const unsigned lam0 = lam1 ^ (lane & 1u);

    {
        const bool cs = lam0;
#pragma unroll
        for (int r = 0; r < 4; r++) {
            u64 t0 = a[r], t1 = a[r | 4];
            a[r]     = cs ? t1 : t0;
            a[r | 4] = cs ? t0 : t1;
        }
    }
    { u64 q = a[4]; a[4] = a[6]; a[6] = q; q = a[5]; a[5] = a[7]; a[7] = q; }
    { u64 q = a[2]; a[2] = a[3]; a[3] = q; q = a[6]; a[6] = a[7]; a[7] = q; }
    // (7,0) step [odd-r exchange mask 24] folded into Round B k=0 operand swap.

    // ===== Round B: per-qubit U = RY(psi1) * RZ(2*hc3) * RY(theta/4) =====
    {
        const int  MSK[5]  = { 24, 12, 6, 3, 1 };
        const unsigned LAMV[5] = { lam4, lam3, lam2, lam1, lam0 };
#pragma unroll
        for (int k = 0; k < NQ; k++) {
            float hc3 = fmaf(0.5f, hc1[k], s_hw[k].y);
            float cd, sd;
            __sincosf(hc3, &sd, &cd);
            float2 pw = s_cs[NQ + k];               // cos/sin(psi1/2)
            float t1 = pw.x * cq[k], t2 = pw.y * sq[k];
            float t3 = pw.x * sq[k], t4 = pw.y * cq[k];
            float P = t1 - t2, Q = t1 + t2, R = t3 + t4, S = t4 - t3;
            float cdP = cd * P, sdQ = sd * Q, cdR = cd * R, sdS = sd * S;
            if (k < 5) {
                const unsigned bb = LAMV[k];
                const float csy = bb ? sdQ : -sdQ;
                const float cpx = bb ? cdR : -cdR;
                const u64 A0 = bc2(cdP), A1 = pk(-csy, csy);
                const u64 B0 = bc2(cpx), B1 = pk(sdS, -sdS);
                __syncwarp();
#pragma unroll
                for (int r = 0; r < 8; r++) slab[r][lane] = a[r];
                __syncwarp();
#pragma unroll
                for (int r = 0; r < 8; r++) {
                    u64 p = slab[r][lane ^ MSK[k]];
                    // k==0 odd regs: ring-1 (7,0) fold -> swap operand roles
                    u64 xs = (k == 0 && (r & 1)) ? p : a[r];
                    u64 ys = (k == 0 && (r & 1)) ? a[r] : p;
                    a[r] = fma2(B1, sw2(ys),
                           fma2(B0, ys,
                           fma2(A1, sw2(xs), mul2(A0, xs))));
                }
            } else {
                const int m = 1 << (7 - k);
                const u64 C0 = bc2(cdP);
                const u64 Cl = pk(sdQ, -sdQ), Ch = pk(-sdQ, sdQ);
                const u64 D0n = bc2(-cdR), D0p = bc2(cdR);
                const u64 D1 = pk(sdS, -sdS);
#pragma unroll
                for (int r = 0; r < 8; r++) {
                    if (!(r & m)) {
                        u64 lo = a[r], hi = a[r | m];
                        u64 swl = sw2(lo), swh = sw2(hi);
                        a[r]     = fma2(D1, swh, fma2(D0n, hi,
                                   fma2(Cl, swl, mul2(C0, lo))));
                        a[r | m] = fma2(Ch, swh, fma2(C0, hi,
                                   fma2(D1, swl, mul2(D0p, lo))));
                    }
                }
            }
        }
    }

    // DIAG4 deleted (diagonal before permutation+measurement = no-op).
    // CNOT ring 2 folded into measurement characters.

    // ===== expectations: <Z_k>_final = <chi_{M_k}>_pre-ring2 =====
    float pwv[8];
#pragma unroll
    for (int r = 0; r < 8; r++) {
        float x, y; upk(a[r], x, y);
        pwv[r] = fmaf(x, x, y * y);
    }
#pragma unroll
    for (int st = 1; st < 8; st <<= 1) {
#pragma unroll
        for (int i = 0; i < 8; i++) {
            if (!(i & st)) {
                float u = pwv[i], v = pwv[i | st];
                pwv[i] = u + v; pwv[i | st] = u - v;
            }
        }
    }
    float v0 = lane_wht(pwv[0], lane);
    float v2 = lane_wht(pwv[2], lane);
    float v4 = lane_wht(pwv[4], lane);
    float v5 = lane_wht(pwv[5], lane);

    float* ob = out + (size_t)b * NQ;
    if (lane == 3)  ob[0] = v2;
    if (lane == 30) ob[1] = v5;
    if (lane == 12) ob[2] = v0;
    if (lane == 6)  { ob[3] = v0; ob[5] = v4; ob[7] = v5; }
    if (lane == 19) { ob[4] = v0; ob[6] = v2; }
}

extern "C" void kernel_launch(void* const* d_in, const int* in_sizes, int n_in,
                              void* d_out, int out_size) {
    const float4* theta4 = (const float4*)d_in[0];
    const float4* phi4   = (const float4*)d_in[1];
    const float4* jup4   = (const float4*)d_in[2];
    const float*  w      = (const float*)d_in[3];
    float* out = (float*)d_out;

    const int grid = (NB * 32) / THREADS;
    vqc_kernel<<<grid, THREADS>>>(theta4, phi4, jup4, w, out);
}

// round 12
// speedup vs baseline: 1.7988x; 1.7988x over previous
#include <cuda_runtime.h>
#include <stdint.h>

#define NQ      8
#define NPAIRS  28
#define NB      16384
#define THREADS 128

typedef unsigned long long u64;

// ---------------- f32x2 packed helpers ----------------
__device__ __forceinline__ u64 pk(float lo, float hi) {
    u64 v; asm("mov.b64 %0, {%1, %2};" : "=l"(v) : "f"(lo), "f"(hi)); return v;
}
__device__ __forceinline__ void upk(u64 v, float& lo, float& hi) {
    asm("mov.b64 {%0, %1}, %2;" : "=f"(lo), "=f"(hi) : "l"(v));
}
__device__ __forceinline__ u64 bc2(float x) { return pk(x, x); }
__device__ __forceinline__ u64 sw2(u64 v) {
    float lo, hi; upk(v, lo, hi); return pk(hi, lo);
}
__device__ __forceinline__ u64 fma2(u64 a, u64 b, u64 c) {
    u64 d; asm("fma.rn.f32x2 %0, %1, %2, %3;" : "=l"(d) : "l"(a), "l"(b), "l"(c)); return d;
}
__device__ __forceinline__ u64 mul2(u64 a, u64 b) {
    u64 d; asm("mul.rn.f32x2 %0, %1, %2;" : "=l"(d) : "l"(a), "l"(b)); return d;
}
__device__ __forceinline__ u64 shflx2(u64 v, int m) {
    float lo, hi; upk(v, lo, hi);
    lo = __shfl_xor_sync(0xffffffffu, lo, m);
    hi = __shfl_xor_sync(0xffffffffu, hi, m);
    return pk(lo, hi);
}

// ---------------- gate primitives ----------------
__device__ __forceinline__ void ry_lane_m(u64 (&a)[8], float c, float s,
                                          int mask, unsigned lam) {
    const u64 c2 = bc2(c);
    const u64 sg2 = bc2(lam ? s : -s);
#pragma unroll
    for (int r = 0; r < 8; r++) {
        u64 p = shflx2(a[r], mask);
        a[r] = fma2(sg2, p, mul2(c2, a[r]));
    }
}

__device__ __forceinline__ void ry_reg_m(u64 (&a)[8], float c, float s, int m) {
    const u64 c2 = bc2(c), s2 = bc2(s), ns2 = bc2(-s);
#pragma unroll
    for (int r = 0; r < 8; r++) {
        if (!(r & m)) {
            u64 x = a[r], y = a[r | m];
            a[r]     = fma2(ns2, y, mul2(c2, x));
            a[r | m] = fma2(s2,  x, mul2(c2, y));
        }
    }
}

__device__ __forceinline__ float lane_wht(float v, unsigned lane) {
#pragma unroll
    for (int m = 1; m < 32; m <<= 1) {
        float t = __shfl_xor_sync(0xffffffffu, v, m);
        v = (lane & m) ? (t - v) : (v + t);
    }
    return v;
}

// ---------------- single fused kernel ----------------

__global__ void __launch_bounds__(THREADS, 8)
vqc_kernel(const float4* __restrict__ theta4, const float4* __restrict__ phi4,
           const float4* __restrict__ jup4, const float* __restrict__ w,
           float* __restrict__ out) {
    // block-shared batch-independent tables
    __shared__ float2 s_cs[2 * NQ];      // cos/sin(theta_w/2) per (layer,qubit)
    __shared__ float2 s_hw[NQ];          // (0.5*phi_w(l0), 0.5*phi_w(l1)-0.25*phi_w(l0))
    __shared__ u64    s_d2t[8][32];      // DIAG2 complex factor, transposed [r][lane]

    const unsigned t    = threadIdx.x;
    const unsigned tid  = blockIdx.x * THREADS + t;
    const unsigned b    = tid >> 5;
    const unsigned lane = tid & 31;

    // ---- cooperative table build ----
    if (t < 2 * NQ) {
        float c, s;
        __sincosf(0.5f * w[t * 3 + 1], &s, &c);
        s_cs[t] = make_float2(c, s);
    } else if (t < 3 * NQ) {
        int i = t - 2 * NQ;
        float w0p = w[i * 3], w1p = w[(NQ + i) * 3];
        s_hw[i] = make_float2(0.5f * w0p, fmaf(-0.25f, w0p, 0.5f * w1p));
    }
    {
        int idx = (int)t * 2;            // even entry; odd differs only in r bit0
        int ln = idx >> 3, r0 = idx & 7;
        float h[8];
#pragma unroll
        for (int k = 0; k < 8; k++) h[k] = 0.5f * w[k * 3 + 2];
        float phr = 0.f;
#pragma unroll
        for (int k = 0; k < 5; k++)
            phr += ((ln >> (4 - k)) & 1) ? h[k] : -h[k];
        phr += ((r0 >> 2) & 1) ? h[5] : -h[5];
        phr += ((r0 >> 1) & 1) ? h[6] : -h[6];
        phr -= h[7];
        float ss, cc;
        __sincosf(phr, &ss, &cc);
        s_d2t[r0][ln] = pk(cc, ss);
        __sincosf(phr + 2.f * h[7], &ss, &cc);
        s_d2t[r0 + 1][ln] = pk(cc, ss);
    }
    __syncthreads();

    // ---- vectorized warp-uniform input loads ----
    float th[NQ], phv[NQ], J[NPAIRS];
    {
        float4 t0 = theta4[b * 2], t1 = theta4[b * 2 + 1];
        th[0]=t0.x; th[1]=t0.y; th[2]=t0.z; th[3]=t0.w;
        th[4]=t1.x; th[5]=t1.y; th[6]=t1.z; th[7]=t1.w;
        float4 p0 = phi4[b * 2], p1 = phi4[b * 2 + 1];
        phv[0]=p0.x; phv[1]=p0.y; phv[2]=p0.z; phv[3]=p0.w;
        phv[4]=p1.x; phv[5]=p1.y; phv[6]=p1.z; phv[7]=p1.w;
#pragma unroll
        for (int q = 0; q < 7; q++) {
            float4 jv = jup4[b * 7 + q];
            J[q*4+0]=jv.x; J[q*4+1]=jv.y; J[q*4+2]=jv.z; J[q*4+3]=jv.w;
        }
    }

    float hc1[NQ];          // 0.5*phi + 0.5*phi_w(l0)
    float cq[NQ], sq[NQ];   // cos/sin(theta/4)
    float ch[NQ], sh[NQ];   // cos/sin(theta/2) via double-angle
#pragma unroll
    for (int k = 0; k < NQ; k++) {
        hc1[k] = fmaf(0.5f, phv[k], s_hw[k].x);
        __sincosf(0.25f * th[k], &sq[k], &cq[k]);
        sh[k] = 2.f * sq[k] * cq[k];
        ch[k] = fmaf(-2.f * sq[k], sq[k], 1.f);
    }

    // ===== Ising Walsh table over reg bits (lane part in index 0) =====
    float exr[8];
    {
        const float HP = 1.5707963267948966f;
        float sg[5];
#pragma unroll
        for (int k = 0; k < 5; k++)
            sg[k] = ((lane >> (4 - k)) & 1) ? 1.f : -1.f;
        float il = 0.f;
        {
            const int PI[10] = {0,0,0,0, 1,1,1, 2,2, 3};
            const int PJ[10] = {1,2,3,4, 2,3,4, 3,4, 4};
            const int PP[10] = {0,1,2,3, 7,8,9, 13,14, 18};
#pragma unroll
            for (int q = 0; q < 10; q++)
                il = fmaf(-sg[PI[q]] * sg[PJ[q]], J[PP[q]], il);
        }
        float U0 = 0.f, U1 = 0.f, U2 = 0.f;
        {
            const int P5[5] = {4, 10, 15, 19, 22};
#pragma unroll
            for (int i = 0; i < 5; i++) {
                U0 = fmaf(sg[i], J[P5[i]],     U0);
                U1 = fmaf(sg[i], J[P5[i] + 1], U1);
                U2 = fmaf(sg[i], J[P5[i] + 2], U2);
            }
        }
        float J56 = J[25], J57 = J[26], J67 = J[27];
        exr[0] = il * HP;  exr[1] = U2 * HP;   exr[2] = U1 * HP;  exr[3] = -J67 * HP;
        exr[4] = U0 * HP;  exr[5] = -J57 * HP; exr[6] = -J56 * HP; exr[7] = 0.f;
    }

    // ===== Fused: product state after encoding RY + DIAG1 phase =====
    u64 a[8];
    {
        float base = 0.f;
#pragma unroll
        for (int k = 0; k < 5; k++)
            base += ((lane >> (4 - k)) & 1) ? hc1[k] : -hc1[k];
        float w0[8];
        w0[0] = base + exr[0];   w0[1] = exr[1] - hc1[7];
        w0[2] = exr[2] - hc1[6]; w0[3] = exr[3];
        w0[4] = exr[4] - hc1[5]; w0[5] = exr[5];
        w0[6] = exr[6];          w0[7] = exr[7];
#pragma unroll
        for (int st = 1; st < 8; st <<= 1) {
#pragma unroll
            for (int i = 0; i < 8; i++) {
                if (!(i & st)) {
                    float u = w0[i], v = w0[i | st];
                    w0[i] = u + v; w0[i | st] = u - v;
                }
            }
        }
        float lf = 1.f;
#pragma unroll
        for (int k = 0; k < 5; k++)
            lf *= ((lane >> (4 - k)) & 1) ? sh[k] : ch[k];
        float f56[4];
        f56[0] = ch[5] * ch[6]; f56[1] = ch[5] * sh[6];
        f56[2] = sh[5] * ch[6]; f56[3] = sh[5] * sh[6];
#pragma unroll
        for (int r = 0; r < 8; r++) {
            float v = lf * f56[r >> 1] * ((r & 1) ? sh[7] : ch[7]);
            float phr = w0[r];
            float q = rintf(phr * 0.15915494309189535f);
            phr = fmaf(q, -6.2831855f, phr);
            float cc, ss;
            __sincosf(phr, &ss, &cc);
            a[r] = pk(v * cc, v * ss);
        }
    }

    // ===== Round A: layer 0 Rot-RY =====
    {
        ry_lane_m(a, s_cs[0].x, s_cs[0].y, 16, (lane >> 4) & 1u);
        ry_lane_m(a, s_cs[1].x, s_cs[1].y,  8, (lane >> 3) & 1u);
        ry_lane_m(a, s_cs[2].x, s_cs[2].y,  4, (lane >> 2) & 1u);
        ry_lane_m(a, s_cs[3].x, s_cs[3].y,  2, (lane >> 1) & 1u);
        ry_lane_m(a, s_cs[4].x, s_cs[4].y,  1,  lane       & 1u);
        ry_reg_m(a, s_cs[5].x, s_cs[5].y, 4);
        ry_reg_m(a, s_cs[6].x, s_cs[6].y, 2);
        ry_reg_m(a, s_cs[7].x, s_cs[7].y, 1);
    }

    // ===== DIAG2 via block-shared complex table (conflict-free LDS.64) =====
#pragma unroll
    for (int r = 0; r < 8; r++) {
        u64 v = s_d2t[r][lane];
        float cc, ss, x, y;
        upk(v, cc, ss); upk(a[r], x, y);
        a[r] = pk(fmaf(cc, x, -ss * y), fmaf(cc, y, ss * x));
    }

    // ===== CNOT ring 1: lane part folded into relabeling =====
    const unsigned lam4 = (lane >> 4) & 1u;
    const unsigned lam3 = lam4 ^ ((lane >> 3) & 1u);
    const unsigned lam2 = lam3 ^ ((lane >> 2) & 1u);
    const unsigned lam1 = lam2 ^ ((lane >> 1) & 1u);
    const unsigned lam0 = lam1 ^ (lane & 1u);

    {
        const bool cs = lam0;
#pragma unroll
        for (int r = 0; r < 4; r++) {
            u64 t0 = a[r], t1 = a[r | 4];
            a[r]     = cs ? t1 : t0;
            a[r | 4] = cs ? t0 : t1;
        }
    }
    { u64 q = a[4]; a[4] = a[6]; a[6] = q; q = a[5]; a[5] = a[7]; a[7] = q; }
    { u64 q = a[2]; a[2] = a[3]; a[3] = q; q = a[6]; a[6] = a[7]; a[7] = q; }
    // (7,0) step [odd-r exchange mask 24] folded into Round B k=0 operand swap.

    // ===== Round B: per-qubit U = RY(psi1) * RZ(2*hc3) * RY(theta/4) =====
    {
        const int  MSK[5]  = { 24, 12, 6, 3, 1 };
        const unsigned LAMV[5] = { lam4, lam3, lam2, lam1, lam0 };
#pragma unroll
        for (int k = 0; k < NQ; k++) {
            float hc3 = fmaf(0.5f, hc1[k], s_hw[k].y);
            float cd, sd;
            __sincosf(hc3, &sd, &cd);
            float2 pw = s_cs[NQ + k];               // cos/sin(psi1/2)
            float t1 = pw.x * cq[k], t2 = pw.y * sq[k];
            float t3 = pw.x * sq[k], t4 = pw.y * cq[k];
            float P = t1 - t2, Q = t1 + t2, R = t3 + t4, S = t4 - t3;
            float cdP = cd * P, sdQ = sd * Q, cdR = cd * R, sdS = sd * S;
            if (k < 5) {
                const unsigned bb = LAMV[k];
                const float csy = bb ? sdQ : -sdQ;
                const float cpx = bb ? cdR : -cdR;
                const u64 A0 = bc2(cdP), A1 = pk(-csy, csy);
                const u64 B0 = bc2(cpx), B1 = pk(sdS, -sdS);
#pragma unroll
                for (int r = 0; r < 8; r++) {
                    u64 p = shflx2(a[r], MSK[k]);
                    // k==0 odd regs: ring-1 (7,0) fold -> swap operand roles
                    u64 xs = (k == 0 && (r & 1)) ? p : a[r];
                    u64 ys = (k == 0 && (r & 1)) ? a[r] : p;
                    a[r] = fma2(B1, sw2(ys),
                           fma2(B0, ys,
                           fma2(A1, sw2(xs), mul2(A0, xs))));
                }
            } else {
                const int m = 1 << (7 - k);
                const u64 C0 = bc2(cdP);
                const u64 Cl = pk(sdQ, -sdQ), Ch = pk(-sdQ, sdQ);
                const u64 D0n = bc2(-cdR), D0p = bc2(cdR);
                const u64 D1 = pk(sdS, -sdS);
#pragma unroll
                for (int r = 0; r < 8; r++) {
                    if (!(r & m)) {
                        u64 lo = a[r], hi = a[r | m];
                        u64 swl = sw2(lo), swh = sw2(hi);
                        a[r]     = fma2(D1, swh, fma2(D0n, hi,
                                   fma2(Cl, swl, mul2(C0, lo))));
                        a[r | m] = fma2(Ch, swh, fma2(C0, hi,
                                   fma2(D1, swl, mul2(D0p, lo))));
                    }
                }
            }
        }
    }

    // DIAG4 deleted (diagonal before permutation+measurement = no-op).
    // CNOT ring 2 folded into measurement characters.

    // ===== expectations: <Z_k>_final = <chi_{M_k}>_pre-ring2 =====
    float pwv[8];
#pragma unroll
    for (int r = 0; r < 8; r++) {
        float x, y; upk(a[r], x, y);
        pwv[r] = fmaf(x, x, y * y);
    }
#pragma unroll
    for (int st = 1; st < 8; st <<= 1) {
#pragma unroll
        for (int i = 0; i < 8; i++) {
            if (!(i & st)) {
                float u = pwv[i], v = pwv[i | st];
                pwv[i] = u + v; pwv[i | st] = u - v;
            }
        }
    }
    float v0 = lane_wht(pwv[0], lane);
    float v2 = lane_wht(pwv[2], lane);
    float v4 = lane_wht(pwv[4], lane);
    float v5 = lane_wht(pwv[5], lane);

    float* ob = out + (size_t)b * NQ;
    if (lane == 3)  ob[0] = v2;
    if (lane == 30) ob[1] = v5;
    if (lane == 12) ob[2] = v0;
    if (lane == 6)  { ob[3] = v0; ob[5] = v4; ob[7] = v5; }
    if (lane == 19) { ob[4] = v0; ob[6] = v2; }
}

extern "C" void kernel_launch(void* const* d_in, const int* in_sizes, int n_in,
                              void* d_out, int out_size) {
    const float4* theta4 = (const float4*)d_in[0];
    const float4* phi4   = (const float4*)d_in[1];
    const float4* jup4   = (const float4*)d_in[2];
    const float*  w      = (const float*)d_in[3];
    float* out = (float*)d_out;

    const int grid = (NB * 32) / THREADS;
    vqc_kernel<<<grid, THREADS>>>(theta4, phi4, jup4, w, out);
}

// round 13
// speedup vs baseline: 1.9064x; 1.0598x over previous
#include <cuda_runtime.h>
#include <stdint.h>

#define NQ      8
#define NPAIRS  28
#define NB      16384
#define THREADS 128

typedef unsigned long long u64;

// ---------------- f32x2 packed helpers ----------------
__device__ __forceinline__ u64 pk(float lo, float hi) {
    u64 v; asm("mov.b64 %0, {%1, %2};" : "=l"(v) : "f"(lo), "f"(hi)); return v;
}
__device__ __forceinline__ void upk(u64 v, float& lo, float& hi) {
    asm("mov.b64 {%0, %1}, %2;" : "=f"(lo), "=f"(hi) : "l"(v));
}
__device__ __forceinline__ u64 bc2(float x) { return pk(x, x); }
__device__ __forceinline__ u64 sw2(u64 v) {
    float lo, hi; upk(v, lo, hi); return pk(hi, lo);
}
__device__ __forceinline__ u64 fma2(u64 a, u64 b, u64 c) {
    u64 d; asm("fma.rn.f32x2 %0, %1, %2, %3;" : "=l"(d) : "l"(a), "l"(b), "l"(c)); return d;
}
__device__ __forceinline__ u64 mul2(u64 a, u64 b) {
    u64 d; asm("mul.rn.f32x2 %0, %1, %2;" : "=l"(d) : "l"(a), "l"(b)); return d;
}
__device__ __forceinline__ u64 shflx2(u64 v, int m) {
    float lo, hi; upk(v, lo, hi);
    lo = __shfl_xor_sync(0xffffffffu, lo, m);
    hi = __shfl_xor_sync(0xffffffffu, hi, m);
    return pk(lo, hi);
}

// ---------------- gate primitives (16 amps/thread) ----------------
__device__ __forceinline__ void ry_lane16(u64 (&a)[16], float c, float s,
                                          int mask, unsigned bit) {
    const u64 c2 = bc2(c);
    const u64 sg2 = bc2(bit ? s : -s);
#pragma unroll
    for (int r = 0; r < 16; r++) {
        u64 p = shflx2(a[r], mask);
        a[r] = fma2(sg2, p, mul2(c2, a[r]));
    }
}

__device__ __forceinline__ void ry_reg16(u64 (&a)[16], float c, float s, int m) {
    const u64 c2 = bc2(c), s2 = bc2(s), ns2 = bc2(-s);
#pragma unroll
    for (int r = 0; r < 16; r++) {
        if (!(r & m)) {
            u64 x = a[r], y = a[r | m];
            a[r]     = fma2(ns2, y, mul2(c2, x));
            a[r | m] = fma2(s2,  x, mul2(c2, y));
        }
    }
}

// 4-step half-warp WHT (masks < 16 keep the two halves independent)
__device__ __forceinline__ float wht4(float v, unsigned lane) {
#pragma unroll
    for (int m = 1; m < 16; m <<= 1) {
        float t = __shfl_xor_sync(0xffffffffu, v, m);
        v = (lane & m) ? (t - v) : (v + t);
    }
    return v;
}

// ---------------- single fused kernel: 16 lanes per state, 2 states/warp ----------------
// State s = l*16 + r.  Lane l bits 3..0 = qubits 0..3; reg r bits 3..0 = qubits 4..7.

__global__ void __launch_bounds__(THREADS, 6)
vqc_kernel(const float4* __restrict__ theta4, const float4* __restrict__ phi4,
           const float4* __restrict__ jup4, const float* __restrict__ w,
           float* __restrict__ out) {
    __shared__ float2 s_cs[2 * NQ];      // cos/sin(theta_w/2) per (layer,qubit)
    __shared__ float2 s_hw[NQ];          // (0.5*phi_w(l0), 0.5*phi_w(l1)-0.25*phi_w(l0))
    __shared__ u64    s_d2t[16][16];     // DIAG2 complex factors [r][l]

    const unsigned t    = threadIdx.x;
    const unsigned lane = t & 31;
    const unsigned l    = lane & 15;
    const unsigned b    = blockIdx.x * 8 + (t >> 5) * 2 + (lane >> 4);

    // ---- cooperative table build ----
    if (t < 2 * NQ) {
        float c, s;
        __sincosf(0.5f * w[t * 3 + 1], &s, &c);
        s_cs[t] = make_float2(c, s);
    } else if (t < 3 * NQ) {
        int i = t - 2 * NQ;
        float w0p = w[i * 3], w1p = w[(NQ + i) * 3];
        s_hw[i] = make_float2(0.5f * w0p, fmaf(-0.25f, w0p, 0.5f * w1p));
    }
    {
        int idx = (int)t * 2;            // 256 entries, 2 per thread (differ in r bit0)
        int lt = idx >> 4, r0 = idx & 15;
        float h[8];
#pragma unroll
        for (int k = 0; k < 8; k++) h[k] = 0.5f * w[k * 3 + 2];
        float phr = 0.f;
#pragma unroll
        for (int k = 0; k < 4; k++)
            phr += ((lt >> (3 - k)) & 1) ? h[k] : -h[k];
        phr += ((r0 >> 3) & 1) ? h[4] : -h[4];
        phr += ((r0 >> 2) & 1) ? h[5] : -h[5];
        phr += ((r0 >> 1) & 1) ? h[6] : -h[6];
        phr -= h[7];                      // r0 bit0 == 0
        float ss, cc;
        __sincosf(phr, &ss, &cc);
        s_d2t[r0][lt] = pk(cc, ss);
        __sincosf(phr + 2.f * h[7], &ss, &cc);
        s_d2t[r0 + 1][lt] = pk(cc, ss);
    }
    __syncthreads();

    // ---- per-state inputs (uniform within each half-warp) ----
    float hc1[8], cq[8], sq[8], ch[8], sh[8];
    float J[NPAIRS];
    {
        float4 t0 = theta4[b * 2], t1 = theta4[b * 2 + 1];
        float th[8] = {t0.x,t0.y,t0.z,t0.w,t1.x,t1.y,t1.z,t1.w};
        float4 p0 = phi4[b * 2], p1 = phi4[b * 2 + 1];
        float phv[8] = {p0.x,p0.y,p0.z,p0.w,p1.x,p1.y,p1.z,p1.w};
#pragma unroll
        for (int q = 0; q < 7; q++) {
            float4 jv = jup4[b * 7 + q];
            J[q*4+0]=jv.x; J[q*4+1]=jv.y; J[q*4+2]=jv.z; J[q*4+3]=jv.w;
        }
#pragma unroll
        for (int k = 0; k < 8; k++) {
            hc1[k] = fmaf(0.5f, phv[k], s_hw[k].x);
            __sincosf(0.25f * th[k], &sq[k], &cq[k]);
            sh[k] = 2.f * sq[k] * cq[k];
            ch[k] = fmaf(-2.f * sq[k], sq[k], 1.f);
        }
    }

    // ===== Ising + DIAG1 Walsh table (16 entries over reg bits) + init product state =====
    u64 a[16];
    {
        const float HP = 1.5707963267948966f;
        float sg[4];
#pragma unroll
        for (int k = 0; k < 4; k++)
            sg[k] = ((l >> (3 - k)) & 1) ? 1.f : -1.f;
        // lane-lane pairs: (0,1)=0 (0,2)=1 (0,3)=2 (1,2)=7 (1,3)=8 (2,3)=13
        float il = 0.f;
        {
            const int PI[6] = {0,0,0,1,1,2};
            const int PJ[6] = {1,2,3,2,3,3};
            const int PP[6] = {0,1,2,7,8,13};
#pragma unroll
            for (int q = 0; q < 6; q++)
                il = fmaf(-sg[PI[q]] * sg[PJ[q]], J[PP[q]], il);
        }
        // lane-reg: (i,4) at {3,9,14,18}; (i,5..7) consecutive
        float U4 = 0.f, U5 = 0.f, U6 = 0.f, U7 = 0.f;
        {
            const int PB[4] = {3, 9, 14, 18};
#pragma unroll
            for (int i = 0; i < 4; i++) {
                U4 = fmaf(sg[i], J[PB[i]],     U4);
                U5 = fmaf(sg[i], J[PB[i] + 1], U5);
                U6 = fmaf(sg[i], J[PB[i] + 2], U6);
                U7 = fmaf(sg[i], J[PB[i] + 3], U7);
            }
        }
        float base = 0.f;
#pragma unroll
        for (int k = 0; k < 4; k++)
            base += ((l >> (3 - k)) & 1) ? hc1[k] : -hc1[k];

        float w0[16];
#pragma unroll
        for (int i = 0; i < 16; i++) w0[i] = 0.f;
        w0[0]  = base + il * HP;
        w0[8]  = fmaf(U4, HP, -hc1[4]);
        w0[4]  = fmaf(U5, HP, -hc1[5]);
        w0[2]  = fmaf(U6, HP, -hc1[6]);
        w0[1]  = fmaf(U7, HP, -hc1[7]);
        // reg-reg: (4,5)=J22@12 (4,6)=J23@10 (4,7)=J24@9 (5,6)=J25@6 (5,7)=J26@5 (6,7)=J27@3
        w0[12] = -J[22] * HP;
        w0[10] = -J[23] * HP;
        w0[9]  = -J[24] * HP;
        w0[6]  = -J[25] * HP;
        w0[5]  = -J[26] * HP;
        w0[3]  = -J[27] * HP;
#pragma unroll
        for (int st = 1; st < 16; st <<= 1) {
#pragma unroll
            for (int i = 0; i < 16; i++) {
                if (!(i & st)) {
                    float u = w0[i], v = w0[i | st];
                    w0[i] = u + v; w0[i | st] = u - v;
                }
            }
        }
        float lf = 1.f;
#pragma unroll
        for (int k = 0; k < 4; k++)
            lf *= ((l >> (3 - k)) & 1) ? sh[k] : ch[k];
        float f45[4] = {ch[4]*ch[5], ch[4]*sh[5], sh[4]*ch[5], sh[4]*sh[5]};
        float f67[4] = {ch[6]*ch[7], ch[6]*sh[7], sh[6]*ch[7], sh[6]*sh[7]};
#pragma unroll
        for (int r = 0; r < 16; r++) {
            float v = lf * f45[r >> 2] * f67[r & 3];
            float phr = w0[r];
            float q = rintf(phr * 0.15915494309189535f);
            phr = fmaf(q, -6.2831855f, phr);
            float cc, ss;
            __sincosf(phr, &ss, &cc);
            a[r] = pk(v * cc, v * ss);
        }
    }

    // ===== Round A: layer 0 Rot-RY (physical mapping) =====
    ry_lane16(a, s_cs[0].x, s_cs[0].y, 8, (l >> 3) & 1u);
    ry_lane16(a, s_cs[1].x, s_cs[1].y, 4, (l >> 2) & 1u);
    ry_lane16(a, s_cs[2].x, s_cs[2].y, 2, (l >> 1) & 1u);
    ry_lane16(a, s_cs[3].x, s_cs[3].y, 1,  l       & 1u);
    ry_reg16(a, s_cs[4].x, s_cs[4].y, 8);
    ry_reg16(a, s_cs[5].x, s_cs[5].y, 4);
    ry_reg16(a, s_cs[6].x, s_cs[6].y, 2);
    ry_reg16(a, s_cs[7].x, s_cs[7].y, 1);

    // ===== DIAG2 via shared table (conflict-free LDS.64, broadcast across halves) =====
#pragma unroll
    for (int r = 0; r < 16; r++) {
        u64 v = s_d2t[r][l];
        float cc, ss, x, y;
        upk(v, cc, ss); upk(a[r], x, y);
        a[r] = pk(fmaf(cc, x, -ss * y), fmaf(cc, y, ss * x));
    }

    // ===== CNOT ring 1 =====
    // (0,1)(1,2)(2,3) folded into lane relabeling (prefix parities lam_j)
    const unsigned lam0 = (l >> 3) & 1u;
    const unsigned lam1 = lam0 ^ ((l >> 2) & 1u);
    const unsigned lam2 = lam1 ^ ((l >> 1) & 1u);
    const unsigned lam3 = lam2 ^ (l & 1u);

    {   // (3,4): ctrl = logical q3 (lam3), tgt = reg bit3
        const bool cs = lam3;
#pragma unroll
        for (int r = 0; r < 8; r++) {
            u64 t0 = a[r], t1 = a[r | 8];
            a[r]     = cs ? t1 : t0;
            a[r | 8] = cs ? t0 : t1;
        }
    }
    // (4,5): reg bit3 ctrl -> flip bit2
    { u64 q; q=a[8];a[8]=a[12];a[12]=q; q=a[9];a[9]=a[13];a[13]=q;
             q=a[10];a[10]=a[14];a[14]=q; q=a[11];a[11]=a[15];a[15]=q; }
    // (5,6): reg bit2 ctrl -> flip bit1
    { u64 q; q=a[4];a[4]=a[6];a[6]=q; q=a[5];a[5]=a[7];a[7]=q;
             q=a[12];a[12]=a[14];a[14]=q; q=a[13];a[13]=a[15];a[15]=q; }
    // (6,7): reg bit1 ctrl -> flip bit0
    { u64 q; q=a[2];a[2]=a[3];a[3]=q; q=a[6];a[6]=a[7];a[7]=q;
             q=a[10];a[10]=a[11];a[11]=q; q=a[14];a[14]=a[15];a[15]=q; }
    // (7,0): odd r, lane mask 12 — folded into Round B k=0 operand swap.

    // ===== Round B: per-qubit U = RY(psi1) * RZ(2*hc3) * RY(theta/4) =====
    {
        const int MSK[4] = {12, 6, 3, 1};
        const unsigned LAMV[4] = {lam0, lam1, lam2, lam3};
#pragma unroll
        for (int k = 0; k < 8; k++) {
            float hc3 = fmaf(0.5f, hc1[k], s_hw[k].y);   // 0.25*phi + 0.5*phi_w(l1)
            float cd, sd;
            __sincosf(hc3, &sd, &cd);
            float2 pw = s_cs[NQ + k];                    // cos/sin(psi1/2)
            float t1 = pw.x * cq[k], t2 = pw.y * sq[k];
            float t3 = pw.x * sq[k], t4 = pw.y * cq[k];
            float P = t1 - t2, Q = t1 + t2, R = t3 + t4, S = t4 - t3;
            float cdP = cd * P, sdQ = sd * Q, cdR = cd * R, sdS = sd * S;
            if (k < 4) {
                const unsigned bb = LAMV[k];
                const float csy = bb ? sdQ : -sdQ;
                const float cpx = bb ? cdR : -cdR;
                const u64 A0 = bc2(cdP), A1 = pk(-csy, csy);
                const u64 B0 = bc2(cpx), B1 = pk(sdS, -sdS);
#pragma unroll
                for (int r = 0; r < 16; r++) {
                    u64 p = shflx2(a[r], MSK[k]);
                    // k==0 odd regs: ring-1 (7,0) fold -> swap operand roles
                    u64 xs = (k == 0 && (r & 1)) ? p : a[r];
                    u64 ys = (k == 0 && (r & 1)) ? a[r] : p;
                    a[r] = fma2(B1, sw2(ys),
                           fma2(B0, ys,
                           fma2(A1, sw2(xs), mul2(A0, xs))));
                }
            } else {
                const int m = 1 << (7 - k);              // 8,4,2,1
                const u64 C0 = bc2(cdP);
                const u64 Cl = pk(sdQ, -sdQ), Ch = pk(-sdQ, sdQ);
                const u64 D0n = bc2(-cdR), D0p = bc2(cdR);
                const u64 D1 = pk(sdS, -sdS);
#pragma unroll
                for (int r = 0; r < 16; r++) {
                    if (!(r & m)) {
                        u64 lo = a[r], hi = a[r | m];
                        u64 swl = sw2(lo), swh = sw2(hi);
                        a[r]     = fma2(D1, swh, fma2(D0n, hi,
                                   fma2(Cl, swl, mul2(C0, lo))));
                        a[r | m] = fma2(Ch, swh, fma2(C0, hi,
                                   fma2(D1, swl, mul2(D0p, lo))));
                    }
                }
            }
        }
    }

    // DIAG4 deleted; CNOT ring 2 folded into measurement characters.
    // Pullback characters with prefix masks P=[8,12,14,15]:
    // Z0:(14,10) Z1:(15,5) Z2:(6,0) Z3:(3,0) Z4:(6,8) Z5:(3,4) Z6:(6,10) Z7:(3,5)
    float pwv[16];
#pragma unroll
    for (int r = 0; r < 16; r++) {
        float x, y; upk(a[r], x, y);
        pwv[r] = fmaf(x, x, y * y);
    }
#pragma unroll
    for (int st = 1; st < 16; st <<= 1) {
#pragma unroll
        for (int i = 0; i < 16; i++) {
            if (!(i & st)) {
                float u = pwv[i], v = pwv[i | st];
                pwv[i] = u + v; pwv[i | st] = u - v;
            }
        }
    }
    float c0  = wht4(pwv[0],  lane);
    float c4  = wht4(pwv[4],  lane);
    float c5  = wht4(pwv[5],  lane);
    float c8  = wht4(pwv[8],  lane);
    float c10 = wht4(pwv[10], lane);

    float* ob = out + (size_t)b * NQ;
    if (l == 14) ob[0] = c10;
    if (l == 15) ob[1] = c5;
    if (l == 6)  { ob[2] = c0; ob[4] = c8; ob[6] = c10; }
    if (l == 3)  { ob[3] = c0; ob[5] = c4; ob[7] = c5; }
}

extern "C" void kernel_launch(void* const* d_in, const int* in_sizes, int n_in,
                              void* d_out, int out_size) {
    const float4* theta4 = (const float4*)d_in[0];
    const float4* phi4   = (const float4*)d_in[1];
    const float4* jup4   = (const float4*)d_in[2];
    const float*  w      = (const float*)d_in[3];
    float* out = (float*)d_out;

    const int grid = NB / 8;   // 8 states per block (4 warps x 2)
    vqc_kernel<<<grid, THREADS>>>(theta4, phi4, jup4, w, out);
}

// round 14
// speedup vs baseline: 2.0467x; 1.0736x over previous
#include <cuda_runtime.h>
#include <stdint.h>

#define NQ      8
#define NPAIRS  28
#define NB      16384
#define THREADS 128

typedef unsigned long long u64;

// ---------------- f32x2 packed helpers ----------------
__device__ __forceinline__ u64 pk(float lo, float hi) {
    u64 v; asm("mov.b64 %0, {%1, %2};" : "=l"(v) : "f"(lo), "f"(hi)); return v;
}
__device__ __forceinline__ void upk(u64 v, float& lo, float& hi) {
    asm("mov.b64 {%0, %1}, %2;" : "=f"(lo), "=f"(hi) : "l"(v));
}
__device__ __forceinline__ u64 bc2(float x) { return pk(x, x); }
__device__ __forceinline__ u64 sw2(u64 v) {
    float lo, hi; upk(v, lo, hi); return pk(hi, lo);
}
__device__ __forceinline__ u64 fma2(u64 a, u64 b, u64 c) {
    u64 d; asm("fma.rn.f32x2 %0, %1, %2, %3;" : "=l"(d) : "l"(a), "l"(b), "l"(c)); return d;
}
__device__ __forceinline__ u64 mul2(u64 a, u64 b) {
    u64 d; asm("mul.rn.f32x2 %0, %1, %2;" : "=l"(d) : "l"(a), "l"(b)); return d;
}
__device__ __forceinline__ u64 shflx2(u64 v, int m) {
    float lo, hi; upk(v, lo, hi);
    lo = __shfl_xor_sync(0xffffffffu, lo, m);
    hi = __shfl_xor_sync(0xffffffffu, hi, m);
    return pk(lo, hi);
}

// ---------------- gate primitives (16 amps/thread) ----------------
__device__ __forceinline__ void ry_lane16(u64 (&a)[16], float c, float s,
                                          int mask, unsigned bit) {
    const u64 c2 = bc2(c);
    const u64 sg2 = bc2(bit ? s : -s);
#pragma unroll
    for (int r = 0; r < 16; r++) {
        u64 p = shflx2(a[r], mask);
        a[r] = fma2(sg2, p, mul2(c2, a[r]));
    }
}

__device__ __forceinline__ void ry_reg16(u64 (&a)[16], float c, float s, int m) {
    const u64 c2 = bc2(c), s2 = bc2(s), ns2 = bc2(-s);
#pragma unroll
    for (int r = 0; r < 16; r++) {
        if (!(r & m)) {
            u64 x = a[r], y = a[r | m];
            a[r]     = fma2(ns2, y, mul2(c2, x));
            a[r | m] = fma2(s2,  x, mul2(c2, y));
        }
    }
}

// 4-step half-warp WHT (masks < 16 keep the two halves independent)
__device__ __forceinline__ float wht4(float v, unsigned lane) {
#pragma unroll
    for (int m = 1; m < 16; m <<= 1) {
        float t = __shfl_xor_sync(0xffffffffu, v, m);
        v = (lane & m) ? (t - v) : (v + t);
    }
    return v;
}

// ---------------- single fused kernel: 16 lanes per state, 2 states/warp ----------------
// State s = l*16 + r.  Lane l bits 3..0 = qubits 0..3; reg r bits 3..0 = qubits 4..7.

__global__ void __launch_bounds__(THREADS, 8)
vqc_kernel(const float4* __restrict__ theta4, const float4* __restrict__ phi4,
           const float4* __restrict__ jup4, const float* __restrict__ w,
           float* __restrict__ out) {
    __shared__ float2 s_cs[2 * NQ];      // cos/sin(theta_w/2) per (layer,qubit)
    __shared__ float2 s_hw[NQ];          // (0.5*phi_w(l0), 0.5*phi_w(l1))
    __shared__ u64    s_d2t[16][16];     // DIAG2 complex factors [r][l]
    __shared__ float4 s_bc[8][8];        // Round-B coeffs [state_in_block][qubit]

    const unsigned t    = threadIdx.x;
    const unsigned lane = t & 31;
    const unsigned l    = lane & 15;
    const unsigned sid  = (t >> 5) * 2 + (lane >> 4);
    const unsigned b    = blockIdx.x * 8 + sid;

    // ---- cooperative table build ----
    if (t < 2 * NQ) {
        float c, s;
        __sincosf(0.5f * w[t * 3 + 1], &s, &c);
        s_cs[t] = make_float2(c, s);
    } else if (t < 3 * NQ) {
        int i = t - 2 * NQ;
        s_hw[i] = make_float2(0.5f * w[i * 3], 0.5f * w[(NQ + i) * 3]);
    }
    {
        int idx = (int)t * 2;            // 256 entries, 2 per thread (differ in r bit0)
        int lt = idx >> 4, r0 = idx & 15;
        float h[8];
#pragma unroll
        for (int k = 0; k < 8; k++) h[k] = 0.5f * w[k * 3 + 2];
        float phr = 0.f;
#pragma unroll
        for (int k = 0; k < 4; k++)
            phr += ((lt >> (3 - k)) & 1) ? h[k] : -h[k];
        phr += ((r0 >> 3) & 1) ? h[4] : -h[4];
        phr += ((r0 >> 2) & 1) ? h[5] : -h[5];
        phr += ((r0 >> 1) & 1) ? h[6] : -h[6];
        phr -= h[7];                      // r0 bit0 == 0
        float ss, cc;
        __sincosf(phr, &ss, &cc);
        s_d2t[r0][lt] = pk(cc, ss);
        __sincosf(phr + 2.f * h[7], &ss, &cc);
        s_d2t[r0 + 1][lt] = pk(cc, ss);
    }
    __syncthreads();

    // ---- per-state inputs (uniform within each half-warp) ----
    float hc1[8], ch[8], sh[8];
    float4 j0, j1, j2, j3, j4, j5, j6;
    {
        float4 t0 = theta4[b * 2], t1 = theta4[b * 2 + 1];
        float th[8] = {t0.x,t0.y,t0.z,t0.w,t1.x,t1.y,t1.z,t1.w};
        float4 p0 = phi4[b * 2], p1 = phi4[b * 2 + 1];
        float phv[8] = {p0.x,p0.y,p0.z,p0.w,p1.x,p1.y,p1.z,p1.w};
        j0 = jup4[b * 7 + 0]; j1 = jup4[b * 7 + 1]; j2 = jup4[b * 7 + 2];
        j3 = jup4[b * 7 + 3]; j4 = jup4[b * 7 + 4]; j5 = jup4[b * 7 + 5];
        j6 = jup4[b * 7 + 6];
#pragma unroll
        for (int k = 0; k < 8; k++) {
            hc1[k] = fmaf(0.5f, phv[k], s_hw[k].x);
            __sincosf(0.5f * th[k], &sh[k], &ch[k]);
        }
        // Parallel Round-B coefficient build: lane j (j<8) handles qubit j.
        if (l < 8) {
            int k = l;
            float cqk, sqk;
            __sincosf(0.25f * th[k], &sqk, &cqk);
            float hc3 = fmaf(0.25f, phv[k], s_hw[k].y);  // 0.25*phi + 0.5*phi_w(l1)
            float cd, sd;
            __sincosf(hc3, &sd, &cd);
            float2 pw = s_cs[NQ + k];                    // cos/sin(psi1/2)
            float t1v = pw.x * cqk, t2v = pw.y * sqk;
            float t3v = pw.x * sqk, t4v = pw.y * cqk;
            float P = t1v - t2v, Q = t1v + t2v, R = t3v + t4v, S = t4v - t3v;
            s_bc[sid][k] = make_float4(cd * P, sd * Q, cd * R, sd * S);
        }
        __syncwarp();
    }

    // ===== Ising + DIAG1 Walsh table + init product state =====
    u64 a[16];
    {
        const float HP = 1.5707963267948966f;
        float sg0 = ((l >> 3) & 1) ? 1.f : -1.f;
        float sg1 = ((l >> 2) & 1) ? 1.f : -1.f;
        float sg2 = ((l >> 1) & 1) ? 1.f : -1.f;
        float sg3 = (l & 1) ? 1.f : -1.f;

        // Scatter each J chunk immediately (lexicographic pair order).
        float il = 0.f, U4 = 0.f, U5 = 0.f, U6 = 0.f, U7 = 0.f;
        il = fmaf(-sg0 * sg1, j0.x, il);   // (0,1)
        il = fmaf(-sg0 * sg2, j0.y, il);   // (0,2)
        il = fmaf(-sg0 * sg3, j0.z, il);   // (0,3)
        U4 = fmaf(sg0, j0.w, U4);          // (0,4)
        U5 = fmaf(sg0, j1.x, U5);          // (0,5)
        U6 = fmaf(sg0, j1.y, U6);          // (0,6)
        U7 = fmaf(sg0, j1.z, U7);          // (0,7)
        il = fmaf(-sg1 * sg2, j1.w, il);   // (1,2)
        il = fmaf(-sg1 * sg3, j2.x, il);   // (1,3)
        U4 = fmaf(sg1, j2.y, U4);          // (1,4)
        U5 = fmaf(sg1, j2.z, U5);          // (1,5)
        U6 = fmaf(sg1, j2.w, U6);          // (1,6)
        U7 = fmaf(sg1, j3.x, U7);          // (1,7)
        il = fmaf(-sg2 * sg3, j3.y, il);   // (2,3)
        U4 = fmaf(sg2, j3.z, U4);          // (2,4)
        U5 = fmaf(sg2, j3.w, U5);          // (2,5)
        U6 = fmaf(sg2, j4.x, U6);          // (2,6)
        U7 = fmaf(sg2, j4.y, U7);          // (2,7)
        U4 = fmaf(sg3, j4.z, U4);          // (3,4)
        U5 = fmaf(sg3, j4.w, U5);          // (3,5)
        U6 = fmaf(sg3, j5.x, U6);          // (3,6)
        U7 = fmaf(sg3, j5.y, U7);          // (3,7)

        float base = 0.f;
#pragma unroll
        for (int k = 0; k < 4; k++)
            base += ((l >> (3 - k)) & 1) ? hc1[k] : -hc1[k];

        float w0[16];
#pragma unroll
        for (int i = 0; i < 16; i++) w0[i] = 0.f;
        w0[0]  = base + il * HP;
        w0[8]  = fmaf(U4, HP, -hc1[4]);
        w0[4]  = fmaf(U5, HP, -hc1[5]);
        w0[2]  = fmaf(U6, HP, -hc1[6]);
        w0[1]  = fmaf(U7, HP, -hc1[7]);
        // reg-reg: (4,5)@12 (4,6)@10 (4,7)@9 (5,6)@6 (5,7)@5 (6,7)@3
        w0[12] = -j5.z * HP;
        w0[10] = -j5.w * HP;
        w0[9]  = -j6.x * HP;
        w0[6]  = -j6.y * HP;
        w0[5]  = -j6.z * HP;
        w0[3]  = -j6.w * HP;
#pragma unroll
        for (int st = 1; st < 16; st <<= 1) {
#pragma unroll
            for (int i = 0; i < 16; i++) {
                if (!(i & st)) {
                    float u = w0[i], v = w0[i | st];
                    w0[i] = u + v; w0[i | st] = u - v;
                }
            }
        }
        float lf = 1.f;
#pragma unroll
        for (int k = 0; k < 4; k++)
            lf *= ((l >> (3 - k)) & 1) ? sh[k] : ch[k];
        float f45[4] = {ch[4]*ch[5], ch[4]*sh[5], sh[4]*ch[5], sh[4]*sh[5]};
        float f67[4] = {ch[6]*ch[7], ch[6]*sh[7], sh[6]*ch[7], sh[6]*sh[7]};
#pragma unroll
        for (int r = 0; r < 16; r++) {
            float v = lf * f45[r >> 2] * f67[r & 3];
            float phr = w0[r];
            float q = rintf(phr * 0.15915494309189535f);
            phr = fmaf(q, -6.2831855f, phr);
            float cc, ss;
            __sincosf(phr, &ss, &cc);
            a[r] = pk(v * cc, v * ss);
        }
    }

    // ===== Round A: layer 0 Rot-RY (physical mapping) =====
    ry_lane16(a, s_cs[0].x, s_cs[0].y, 8, (l >> 3) & 1u);
    ry_lane16(a, s_cs[1].x, s_cs[1].y, 4, (l >> 2) & 1u);
    ry_lane16(a, s_cs[2].x, s_cs[2].y, 2, (l >> 1) & 1u);
    ry_lane16(a, s_cs[3].x, s_cs[3].y, 1,  l       & 1u);
    ry_reg16(a, s_cs[4].x, s_cs[4].y, 8);
    ry_reg16(a, s_cs[5].x, s_cs[5].y, 4);
    ry_reg16(a, s_cs[6].x, s_cs[6].y, 2);
    ry_reg16(a, s_cs[7].x, s_cs[7].y, 1);

    // ===== DIAG2 via shared table (conflict-free LDS.64, broadcast across halves) =====
#pragma unroll
    for (int r = 0; r < 16; r++) {
        u64 v = s_d2t[r][l];
        float cc, ss, x, y;
        upk(v, cc, ss); upk(a[r], x, y);
        a[r] = pk(fmaf(cc, x, -ss * y), fmaf(cc, y, ss * x));
    }

    // ===== CNOT ring 1 =====
    const unsigned lam0 = (l >> 3) & 1u;
    const unsigned lam1 = lam0 ^ ((l >> 2) & 1u);
    const unsigned lam2 = lam1 ^ ((l >> 1) & 1u);
    const unsigned lam3 = lam2 ^ (l & 1u);

    {   // (3,4): ctrl = logical q3 (lam3), tgt = reg bit3
        const bool cs = lam3;
#pragma unroll
        for (int r = 0; r < 8; r++) {
            u64 t0 = a[r], t1 = a[r | 8];
            a[r]     = cs ? t1 : t0;
            a[r | 8] = cs ? t0 : t1;
        }
    }
    // (4,5): reg bit3 ctrl -> flip bit2
    { u64 q; q=a[8];a[8]=a[12];a[12]=q; q=a[9];a[9]=a[13];a[13]=q;
             q=a[10];a[10]=a[14];a[14]=q; q=a[11];a[11]=a[15];a[15]=q; }
    // (5,6): reg bit2 ctrl -> flip bit1
    { u64 q; q=a[4];a[4]=a[6];a[6]=q; q=a[5];a[5]=a[7];a[7]=q;
             q=a[12];a[12]=a[14];a[14]=q; q=a[13];a[13]=a[15];a[15]=q; }
    // (6,7): reg bit1 ctrl -> flip bit0
    { u64 q; q=a[2];a[2]=a[3];a[3]=q; q=a[6];a[6]=a[7];a[7]=q;
             q=a[10];a[10]=a[11];a[11]=q; q=a[14];a[14]=a[15];a[15]=q; }
    // (7,0): odd r, lane mask 12 — folded into Round B k=0 operand swap.

    // ===== Round B: per-qubit U (coeffs from SMEM) =====
    {
        const int MSK[4] = {12, 6, 3, 1};
        const unsigned LAMV[4] = {lam0, lam1, lam2, lam3};
#pragma unroll
        for (int k = 0; k < 8; k++) {
            float4 cf = s_bc[sid][k];                 // cdP, sdQ, cdR, sdS
            float cdP = cf.x, sdQ = cf.y, cdR = cf.z, sdS = cf.w;
            if (k < 4) {
                const unsigned bb = LAMV[k];
                const float csy = bb ? sdQ : -sdQ;
                const float cpx = bb ? cdR : -cdR;
                const u64 A0 = bc2(cdP), A1 = pk(-csy, csy);
                const u64 B0 = bc2(cpx), B1 = pk(sdS, -sdS);
#pragma unroll
                for (int r = 0; r < 16; r++) {
                    u64 p = shflx2(a[r], MSK[k]);
                    // k==0 odd regs: ring-1 (7,0) fold -> swap operand roles
                    u64 xs = (k == 0 && (r & 1)) ? p : a[r];
                    u64 ys = (k == 0 && (r & 1)) ? a[r] : p;
                    a[r] = fma2(B1, sw2(ys),
                           fma2(B0, ys,
                           fma2(A1, sw2(xs), mul2(A0, xs))));
                }
            } else {
                const int m = 1 << (7 - k);              // 8,4,2,1
                const u64 C0 = bc2(cdP);
                const u64 Cl = pk(sdQ, -sdQ), Ch = pk(-sdQ, sdQ);
                const u64 D0n = bc2(-cdR), D0p = bc2(cdR);
                const u64 D1 = pk(sdS, -sdS);
#pragma unroll
                for (int r = 0; r < 16; r++) {
                    if (!(r & m)) {
                        u64 lo = a[r], hi = a[r | m];
                        u64 swl = sw2(lo), swh = sw2(hi);
                        a[r]     = fma2(D1, swh, fma2(D0n, hi,
                                   fma2(Cl, swl, mul2(C0, lo))));
                        a[r | m] = fma2(Ch, swh, fma2(C0, hi,
                                   fma2(D1, swl, mul2(D0p, lo))));
                    }
                }
            }
        }
    }

    // DIAG4 deleted; CNOT ring 2 folded into measurement characters.
    // Z0:(14,10) Z1:(15,5) Z2:(6,0) Z3:(3,0) Z4:(6,8) Z5:(3,4) Z6:(6,10) Z7:(3,5)
    float pwv[16];
#pragma unroll
    for (int r = 0; r < 16; r++) {
        float x, y; upk(a[r], x, y);
        pwv[r] = fmaf(x, x, y * y);
    }
#pragma unroll
    for (int st = 1; st < 16; st <<= 1) {
#pragma unroll
        for (int i = 0; i < 16; i++) {
            if (!(i & st)) {
                float u = pwv[i], v = pwv[i | st];
                pwv[i] = u + v; pwv[i | st] = u - v;
            }
        }
    }
    float c0  = wht4(pwv[0],  lane);
    float c4  = wht4(pwv[4],  lane);
    float c5  = wht4(pwv[5],  lane);
    float c8  = wht4(pwv[8],  lane);
    float c10 = wht4(pwv[10], lane);

    float* ob = out + (size_t)b * NQ;
    if (l == 14) ob[0] = c10;
    if (l == 15) ob[1] = c5;
    if (l == 6)  { ob[2] = c0; ob[4] = c8; ob[6] = c10; }
    if (l == 3)  { ob[3] = c0; ob[5] = c4; ob[7] = c5; }
}

extern "C" void kernel_launch(void* const* d_in, const int* in_sizes, int n_in,
                              void* d_out, int out_size) {
    const float4* theta4 = (const float4*)d_in[0];
    const float4* phi4   = (const float4*)d_in[1];
    const float4* jup4   = (const float4*)d_in[2];
    const float*  w      = (const float*)d_in[3];
    float* out = (float*)d_out;

    const int grid = NB / 8;   // 8 states per block (4 warps x 2)
    vqc_kernel<<<grid, THREADS>>>(theta4, phi4, jup4, w, out);
}